// round 5
// baseline (speedup 1.0000x reference)
#include <cuda_runtime.h>
#include <math.h>

// Problem dims (fixed by the reference)
#define BB  8
#define HH  384
#define WW  768
#define HW_ (HH * WW)        // 294912
#define BHW (BB * HW_)       // 2359296

typedef unsigned long long u64;

// ---------------------------------------------------------------------------
// Scratch (static __device__ arrays: no runtime allocation)
// ---------------------------------------------------------------------------
__device__ double g_acc[6];
// 0: photo_fw_sum, 1: photo_bw_sum, 2: mask_fw_sum, 3: mask_bw_sum,
// 4: census_fw_sum, 5: census_bw_sum

__device__ float g_inten1 [BHW];  // gray(img1)*255
__device__ float g_inten2w[BHW];  // gray(warp(img2, flow_fw))*255
__device__ float g_inten2 [BHW];  // gray(img2)*255
__device__ float g_inten1w[BHW];  // gray(warp(img1, flow_bw))*255
__device__ float g_mask_fw[BHW];
__device__ float g_mask_bw[BHW];

// ---------------------------------------------------------------------------
// Packed f32x2 helpers (sm_103a FFMA2 path — only reachable via PTX)
// ---------------------------------------------------------------------------
__device__ __forceinline__ u64 pk(float lo, float hi) {
    u64 r; asm("mov.b64 %0, {%1, %2};" : "=l"(r) : "f"(lo), "f"(hi)); return r;
}
__device__ __forceinline__ void unpk(u64 v, float& lo, float& hi) {
    asm("mov.b64 {%0, %1}, %2;" : "=f"(lo), "=f"(hi) : "l"(v));
}
__device__ __forceinline__ u64 f2fma(u64 a, u64 b, u64 c) {
    u64 d; asm("fma.rn.f32x2 %0, %1, %2, %3;" : "=l"(d) : "l"(a), "l"(b), "l"(c)); return d;
}
__device__ __forceinline__ u64 f2mul(u64 a, u64 b) {
    u64 d; asm("mul.rn.f32x2 %0, %1, %2;" : "=l"(d) : "l"(a), "l"(b)); return d;
}
__device__ __forceinline__ u64 f2add(u64 a, u64 b) {
    u64 d; asm("add.rn.f32x2 %0, %1, %2;" : "=l"(d) : "l"(a), "l"(b)); return d;
}
__device__ __forceinline__ u64 f2sqrt(u64 a) {  // per-element MUFU sqrt
    float lo, hi; unpk(a, lo, hi);
    float sl, sh;
    asm("sqrt.approx.f32 %0, %1;" : "=f"(sl) : "f"(lo));
    asm("sqrt.approx.f32 %0, %1;" : "=f"(sh) : "f"(hi));
    return pk(sl, sh);
}
__device__ __forceinline__ u64 f2rcp(u64 a) {   // per-element MUFU rcp
    float lo, hi; unpk(a, lo, hi);
    float rl, rh;
    asm("rcp.approx.f32 %0, %1;" : "=f"(rl) : "f"(lo));
    asm("rcp.approx.f32 %0, %1;" : "=f"(rh) : "f"(hi));
    return pk(rl, rh);
}

// ---------------------------------------------------------------------------
// Scalar helpers
// ---------------------------------------------------------------------------
__device__ __forceinline__ float warp_red(float v) {
#pragma unroll
    for (int o = 16; o > 0; o >>= 1) v += __shfl_down_sync(0xFFFFFFFFu, v, o);
    return v;
}

// bilinear coords (align_corners=True, border padding == clamp)
__device__ __forceinline__ void bilin(float gx, float gy,
                                      int& i00, int& i01, int& i10, int& i11,
                                      float& w00, float& w01, float& w10, float& w11) {
    gx = fminf(fmaxf(gx, 0.0f), (float)(WW - 1));
    gy = fminf(fmaxf(gy, 0.0f), (float)(HH - 1));
    float x0 = floorf(gx);
    float y0 = floorf(gy);
    float wx = gx - x0;
    float wy = gy - y0;
    int x0i = (int)x0;
    int y0i = (int)y0;
    int x1i = min(x0i + 1, WW - 1);
    int y1i = min(y0i + 1, HH - 1);
    i00 = y0i * WW + x0i;
    i01 = y0i * WW + x1i;
    i10 = y1i * WW + x0i;
    i11 = y1i * WW + x1i;
    w00 = (1.0f - wx) * (1.0f - wy);
    w01 = wx * (1.0f - wy);
    w10 = (1.0f - wx) * wy;
    w11 = wx * wy;
}

__device__ __forceinline__ float gather4(const float* __restrict__ p,
                                         int i00, int i01, int i10, int i11,
                                         float w00, float w01, float w10, float w11) {
    return __ldg(p + i00) * w00 + __ldg(p + i01) * w01 +
           __ldg(p + i10) * w10 + __ldg(p + i11) * w11;
}

// ---------------------------------------------------------------------------
// K0: zero accumulators
// ---------------------------------------------------------------------------
__global__ void k_zero() {
    if (threadIdx.x < 6) g_acc[threadIdx.x] = 0.0;
}

// ---------------------------------------------------------------------------
// K1: warps, occlusion masks, photometric loss terms, intensity planes
// ---------------------------------------------------------------------------
__global__ __launch_bounds__(256) void k_warp(
    const float* __restrict__ img1, const float* __restrict__ img2,
    const float* __restrict__ ffw,  const float* __restrict__ fbw,
    float* __restrict__ occ_out) {

    const int idx = blockIdx.x * blockDim.x + threadIdx.x;  // < BHW exactly
    const int b = idx / HW_;
    const int r = idx - b * HW_;
    const int y = r / WW;
    const int x = r - y * WW;

    const float* ffb = ffw + b * 2 * HW_;
    const float* fbb = fbw + b * 2 * HW_;
    const float ffx = __ldg(ffb + r);
    const float ffy = __ldg(ffb + HW_ + r);
    const float fbx = __ldg(fbb + r);
    const float fby = __ldg(fbb + HW_ + r);

    // ---- forward-flow coordinates: warp img2 and flow_bw ----
    int a00, a01, a10, a11; float u00, u01, u10, u11;
    bilin(ffx + (float)x, ffy + (float)y, a00, a01, a10, a11, u00, u01, u10, u11);
    const float* i2b = img2 + b * 3 * HW_;
    float i2w0 = gather4(i2b,            a00, a01, a10, a11, u00, u01, u10, u11);
    float i2w1 = gather4(i2b + HW_,      a00, a01, a10, a11, u00, u01, u10, u11);
    float i2w2 = gather4(i2b + 2 * HW_,  a00, a01, a10, a11, u00, u01, u10, u11);
    float fbw_wx = gather4(fbb,          a00, a01, a10, a11, u00, u01, u10, u11);
    float fbw_wy = gather4(fbb + HW_,    a00, a01, a10, a11, u00, u01, u10, u11);

    // ---- backward-flow coordinates: warp img1 and flow_fw ----
    int c00, c01, c10, c11; float v00, v01, v10, v11;
    bilin(fbx + (float)x, fby + (float)y, c00, c01, c10, c11, v00, v01, v10, v11);
    const float* i1b = img1 + b * 3 * HW_;
    float i1w0 = gather4(i1b,            c00, c01, c10, c11, v00, v01, v10, v11);
    float i1w1 = gather4(i1b + HW_,      c00, c01, c10, c11, v00, v01, v10, v11);
    float i1w2 = gather4(i1b + 2 * HW_,  c00, c01, c10, c11, v00, v01, v10, v11);
    float ffw_wx = gather4(ffb,          c00, c01, c10, c11, v00, v01, v10, v11);
    float ffw_wy = gather4(ffb + HW_,    c00, c01, c10, c11, v00, v01, v10, v11);

    // ---- occlusion masks ----
    float d0 = ffx + fbw_wx, d1 = ffy + fbw_wy;
    float mag_f = d0 * d0 + d1 * d1;
    float fm_f = (ffx * ffx + ffy * ffy) + (fbw_wx * fbw_wx + fbw_wy * fbw_wy);
    float occ_f = (mag_f > 0.01f * fm_f + 0.5f) ? 1.0f : 0.0f;
    float mfw = 1.0f - occ_f;

    float e0 = fbx + ffw_wx, e1 = fby + ffw_wy;
    float mag_b = e0 * e0 + e1 * e1;
    float fm_b = (fbx * fbx + fby * fby) + (ffw_wx * ffw_wx + ffw_wy * ffw_wy);
    float occ_b = (mag_b > 0.01f * fm_b + 0.5f) ? 1.0f : 0.0f;
    float mbw = 1.0f - occ_b;

    // ---- photometric terms ----
    float i1c0 = __ldg(i1b + r);
    float i1c1 = __ldg(i1b + HW_ + r);
    float i1c2 = __ldg(i1b + 2 * HW_ + r);
    float i2c0 = __ldg(i2b + r);
    float i2c1 = __ldg(i2b + HW_ + r);
    float i2c2 = __ldg(i2b + 2 * HW_ + r);

    float pfw = (__powf(fabsf(i1c0 - i2w0) + 0.01f, 0.4f) +
                 __powf(fabsf(i1c1 - i2w1) + 0.01f, 0.4f) +
                 __powf(fabsf(i1c2 - i2w2) + 0.01f, 0.4f)) * mfw;
    float pbw = (__powf(fabsf(i2c0 - i1w0) + 0.01f, 0.4f) +
                 __powf(fabsf(i2c1 - i1w1) + 0.01f, 0.4f) +
                 __powf(fabsf(i2c2 - i1w2) + 0.01f, 0.4f)) * mbw;

    // ---- intensity planes (gray*255) ----
    g_inten1 [idx] = (0.2989f * i1c0 + 0.587f * i1c1 + 0.114f * i1c2) * 255.0f;
    g_inten2 [idx] = (0.2989f * i2c0 + 0.587f * i2c1 + 0.114f * i2c2) * 255.0f;
    g_inten2w[idx] = (0.2989f * i2w0 + 0.587f * i2w1 + 0.114f * i2w2) * 255.0f;
    g_inten1w[idx] = (0.2989f * i1w0 + 0.587f * i1w1 + 0.114f * i1w2) * 255.0f;
    g_mask_fw[idx] = mfw;
    g_mask_bw[idx] = mbw;
    occ_out[idx] = occ_f;

    // ---- block reduce 4 scalars, one double atomic each per block ----
    __shared__ float red[4][8];
    const int wid = threadIdx.x >> 5;
    const int lane = threadIdx.x & 31;
    float vals[4] = {pfw, pbw, mfw, mbw};
#pragma unroll
    for (int i = 0; i < 4; i++) {
        float v = warp_red(vals[i]);
        if (lane == 0) red[i][wid] = v;
    }
    __syncthreads();
    if (wid == 0) {
#pragma unroll
        for (int i = 0; i < 4; i++) {
            float v = (lane < 8) ? red[i][lane] : 0.0f;
            v = warp_red(v);
            if (lane == 0) atomicAdd(&g_acc[i], (double)v);
        }
    }
}

// ---------------------------------------------------------------------------
// K2: census loss, f32x2-packed (2 vertically-adjacent pixels per thread).
// grid = (W/32, H/16, 2*B), block = (32, 8) -> tile 32x16 pixels.
//
// Per tap, instead of tA = u*rsqrt(0.81+u^2), tB = v*rsqrt(0.81+v^2),
// q = (tA-tB)^2, dist = q/(0.1+q)   [3 MUFU],
// use  N = q*P = u^2*pv + v^2*pu - 2uv*sqrt(P),  P = pu*pv,
//      dist = N / (0.1*P + N)                     [2 MUFU: sqrt + rcp].
// ---------------------------------------------------------------------------
__global__ __launch_bounds__(256) void k_census() {
    const int z = blockIdx.z;
    const int b = z & 7;
    const int pair = z >> 3;

    const float* __restrict__ A  = (pair ? g_inten2  : g_inten1 ) + b * HW_;
    const float* __restrict__ Bp = (pair ? g_inten1w : g_inten2w) + b * HW_;
    const float* __restrict__ M  = (pair ? g_mask_bw : g_mask_fw) + b * HW_;

    __shared__ float sA[22][38];
    __shared__ float sB[22][38];

    const int gx0 = blockIdx.x * 32 - 3;
    const int gy0 = blockIdx.y * 16 - 3;
    const int tid = threadIdx.y * 32 + threadIdx.x;

    for (int i = tid; i < 22 * 38; i += 256) {
        int ly = i / 38;
        int lx = i - ly * 38;
        int gy = gy0 + ly;
        int gx = gx0 + lx;
        bool in = (gx >= 0) & (gx < WW) & (gy >= 0) & (gy < HH);
        int g = gy * WW + gx;
        sA[ly][lx] = in ? __ldg(A + g) : 0.0f;
        sB[ly][lx] = in ? __ldg(Bp + g) : 0.0f;
    }
    __syncthreads();

    const int tx  = threadIdx.x;
    const int ty2 = threadIdx.y * 2;   // pixel0 local row; pixel1 = ty2+1
    // pixel0 shared center: sA[ty2+3][tx+3]; pixel1: sA[ty2+4][tx+3]

    const u64 negA = pk(-sA[ty2 + 3][tx + 3], -sA[ty2 + 4][tx + 3]);
    const u64 negB = pk(-sB[ty2 + 3][tx + 3], -sB[ty2 + 4][tx + 3]);
    const u64 C081 = pk(0.81f, 0.81f);
    const u64 C01  = pk(0.1f, 0.1f);
    const u64 CM2  = pk(-2.0f, -2.0f);

    float curA[7], curB[7], nxtA[7], nxtB[7];
#pragma unroll
    for (int dx = 0; dx < 7; dx++) {
        curA[dx] = sA[ty2][tx + dx];
        curB[dx] = sB[ty2][tx + dx];
    }

    u64 acc = pk(0.0f, 0.0f);
#pragma unroll
    for (int dy = 0; dy < 7; dy++) {
#pragma unroll
        for (int dx = 0; dx < 7; dx++) {
            nxtA[dx] = sA[ty2 + dy + 1][tx + dx];
            nxtB[dx] = sB[ty2 + dy + 1][tx + dx];
        }
#pragma unroll
        for (int dx = 0; dx < 7; dx++) {
            if (dy == 3 && dx == 3) continue;  // center tap (both lanes) == 0
            u64 u  = f2add(pk(curA[dx], nxtA[dx]), negA);
            u64 v  = f2add(pk(curB[dx], nxtB[dx]), negB);
            u64 pu = f2fma(u, u, C081);
            u64 pv = f2fma(v, v, C081);
            u64 P  = f2mul(pu, pv);
            u64 s  = f2sqrt(P);                 // 2x MUFU sqrt
            u64 uv = f2mul(u, v);
            u64 t  = f2mul(uv, CM2);            // -2uv
            u64 u2 = f2mul(u, u);
            u64 v2 = f2mul(v, v);
            u64 n1 = f2mul(u2, pv);
            u64 N  = f2fma(v2, pu, n1);
            N      = f2fma(t, s, N);            // N = q * P  >= 0
            u64 dn = f2fma(P, C01, N);          // 0.1*P + N
            u64 r  = f2rcp(dn);                 // 2x MUFU rcp
            acc    = f2fma(N, r, acc);
        }
#pragma unroll
        for (int dx = 0; dx < 7; dx++) {
            curA[dx] = nxtA[dx];
            curB[dx] = nxtB[dx];
        }
    }

    float a0, a1;
    unpk(acc, a0, a1);
    const int px  = blockIdx.x * 32 + tx;
    const int py0 = blockIdx.y * 16 + ty2;
    float m0 = __ldg(M + py0 * WW + px);
    float m1 = __ldg(M + (py0 + 1) * WW + px);
    float val = __powf(a0 + 0.01f, 0.4f) * m0 + __powf(a1 + 0.01f, 0.4f) * m1;

    // block reduce -> one double atomic
    __shared__ float red[8];
    const int wid = tid >> 5;
    const int lane = tid & 31;
    float v = warp_red(val);
    if (lane == 0) red[wid] = v;
    __syncthreads();
    if (wid == 0) {
        float w = (lane < 8) ? red[lane] : 0.0f;
        w = warp_red(w);
        if (lane == 0) atomicAdd(&g_acc[4 + pair], (double)w);
    }
}

// ---------------------------------------------------------------------------
// K3: finalize scalars
// ---------------------------------------------------------------------------
__global__ void k_final(float* __restrict__ out) {
    double den_fw = 2.0 * g_acc[2] + 1e-6;
    double den_bw = 2.0 * g_acc[3] + 1e-6;
    double photo  = g_acc[0] / den_fw + g_acc[1] / den_bw;
    double census = g_acc[4] / den_fw + g_acc[5] / den_bw;
    out[0] = (float)(photo + census);
    out[1] = (float)photo;
    out[2] = (float)census;
}

// ---------------------------------------------------------------------------
// Launch
// ---------------------------------------------------------------------------
extern "C" void kernel_launch(void* const* d_in, const int* in_sizes, int n_in,
                              void* d_out, int out_size) {
    const float* img1 = (const float*)d_in[0];
    const float* img2 = (const float*)d_in[1];
    const float* ffw  = (const float*)d_in[2];
    const float* fbw  = (const float*)d_in[3];
    float* out = (float*)d_out;

    (void)in_sizes; (void)n_in; (void)out_size;

    k_zero<<<1, 32>>>();
    k_warp<<<BHW / 256, 256>>>(img1, img2, ffw, fbw, out + 3);
    dim3 g2(WW / 32, HH / 16, 2 * BB);
    dim3 b2(32, 8, 1);
    k_census<<<g2, b2>>>();
    k_final<<<1, 1>>>(out);
}